// round 1
// baseline (speedup 1.0000x reference)
#include <cuda_runtime.h>
#include <math.h>

#define N_MAX 50000
#define E_MAX 1600000
#define EP_MAX (E_MAX + N_MAX)

// ---------------- scratch (static device globals; no runtime alloc) ----------
__device__ float g_xlr[N_MAX * 128];   // [xl | xr] per node, 128 floats/row
__device__ float g_h[N_MAX * 64];      // layer output
__device__ int   g_rowptr[N_MAX + 1];
__device__ int   g_deg[N_MAX];
__device__ int   g_fill[N_MAX];
__device__ float g_asum[N_MAX];
__device__ int   g_colsrc[EP_MAX];
__device__ float g_colea[EP_MAX];
__device__ float g_Wcat[128 * 128];
__device__ float g_bcat[128];
__device__ float g_pooled[64 * 64];

// ---------------- CSR build ----------------
__global__ void zero_kernel(int n) {
    int i = blockIdx.x * blockDim.x + threadIdx.x;
    if (i < n) { g_deg[i] = 0; g_fill[i] = 0; g_asum[i] = 0.0f; }
}

__global__ void edge_stats_kernel(const int* __restrict__ dst,
                                  const float* __restrict__ ea, int E) {
    int e = blockIdx.x * blockDim.x + threadIdx.x;
    if (e < E) {
        int d = dst[e];
        atomicAdd(&g_deg[d], 1);
        atomicAdd(&g_asum[d], ea[e]);
    }
}

// single-block exclusive scan of (deg[i]+1) -> rowptr
__global__ void scan_kernel(int n) {
    __shared__ int warp_sums[32];
    __shared__ int s_carry;
    int tid = threadIdx.x, lane = tid & 31, wid = tid >> 5;
    if (tid == 0) s_carry = 0;
    __syncthreads();
    for (int base = 0; base < n; base += blockDim.x) {
        int i = base + tid;
        int v = (i < n) ? (g_deg[i] + 1) : 0;
        int x = v;
        #pragma unroll
        for (int o = 1; o < 32; o <<= 1) {
            int y = __shfl_up_sync(0xffffffffu, x, o);
            if (lane >= o) x += y;
        }
        if (lane == 31) warp_sums[wid] = x;
        __syncthreads();
        if (wid == 0) {
            int ws = warp_sums[lane];
            #pragma unroll
            for (int o = 1; o < 32; o <<= 1) {
                int y = __shfl_up_sync(0xffffffffu, ws, o);
                if (lane >= o) ws += y;
            }
            warp_sums[lane] = ws;
        }
        __syncthreads();
        int warp_off = (wid > 0) ? warp_sums[wid - 1] : 0;
        int incl = x + warp_off;
        int excl = incl - v + s_carry;
        if (i < n) g_rowptr[i] = excl;
        __syncthreads();
        if (tid == blockDim.x - 1) s_carry += incl;
        __syncthreads();
    }
    if (threadIdx.x == 0) g_rowptr[n] = s_carry;
}

__global__ void scatter_kernel(const int* __restrict__ src, const int* __restrict__ dst,
                               const float* __restrict__ ea, int E, int n) {
    int idx = blockIdx.x * blockDim.x + threadIdx.x;
    if (idx < E) {
        int d = dst[idx];
        int pos = g_rowptr[d] + atomicAdd(&g_fill[d], 1);
        g_colsrc[pos] = src[idx];
        g_colea[pos] = ea[idx];
    } else if (idx < E + n) {
        int i = idx - E;                    // self loop at last slot of node i
        int pos = g_rowptr[i + 1] - 1;
        g_colsrc[pos] = i;
        g_colea[pos]  = g_asum[i] / fmaxf((float)g_deg[i], 1.0f);
    }
}

// ---------------- weight concat: Wcat = [Wl | Wr] (K x 128), bcat = [bl | br] --
__global__ void wprep_kernel(const float* __restrict__ Wl, const float* __restrict__ bl,
                             const float* __restrict__ Wr, const float* __restrict__ br,
                             int K) {
    int i = blockIdx.x * blockDim.x + threadIdx.x;
    if (i < K * 128) {
        int k = i >> 7, c = i & 127;
        g_Wcat[i] = (c < 64) ? Wl[k * 64 + c] : Wr[k * 64 + (c - 64)];
    }
    if (i < 128) g_bcat[i] = (i < 64) ? bl[i] : br[i - 64];
}

// ---------------- tiled SGEMM: C[n x 128] = A[n x K] @ Wcat + bcat -> g_xlr ---
// BM=64, BN=128, BK=16, 256 threads, 4x8 register tile per thread.
__global__ void sgemm_kernel(const float* __restrict__ Ain, int n, int K, int use_h) {
    const float* A = use_h ? (const float*)g_h : Ain;
    __shared__ float As[16][64];
    __shared__ float Ws[16][128];
    int tid = threadIdx.x;
    int block_m = blockIdx.x * 64;
    int tr = tid >> 4;   // 0..15 -> rows tr*4..tr*4+3
    int tc = tid & 15;   // 0..15 -> cols tc*8..tc*8+7
    float acc[4][8];
    #pragma unroll
    for (int i = 0; i < 4; i++)
        #pragma unroll
        for (int j = 0; j < 8; j++) acc[i][j] = 0.0f;

    for (int k0 = 0; k0 < K; k0 += 16) {
        // A tile: 64 rows x 16 k, float4 per thread
        {
            int r = tid >> 2;
            int kk = (tid & 3) * 4;
            int row = block_m + r;
            float4 v = make_float4(0.f, 0.f, 0.f, 0.f);
            if (row < n) v = *(const float4*)&A[row * K + k0 + kk];
            As[kk + 0][r] = v.x; As[kk + 1][r] = v.y;
            As[kk + 2][r] = v.z; As[kk + 3][r] = v.w;
        }
        // W tile: 16 x 128, 8 floats per thread
        {
            int l = tid * 8;
            int kk = l >> 7, c = l & 127;
            float4 w0 = *(const float4*)&g_Wcat[(k0 + kk) * 128 + c];
            float4 w1 = *(const float4*)&g_Wcat[(k0 + kk) * 128 + c + 4];
            *(float4*)&Ws[kk][c] = w0;
            *(float4*)&Ws[kk][c + 4] = w1;
        }
        __syncthreads();
        #pragma unroll
        for (int kk = 0; kk < 16; kk++) {
            float a[4];
            #pragma unroll
            for (int i = 0; i < 4; i++) a[i] = As[kk][tr * 4 + i];
            float4 w0 = *(float4*)&Ws[kk][tc * 8];
            float4 w1 = *(float4*)&Ws[kk][tc * 8 + 4];
            float w[8] = {w0.x, w0.y, w0.z, w0.w, w1.x, w1.y, w1.z, w1.w};
            #pragma unroll
            for (int i = 0; i < 4; i++)
                #pragma unroll
                for (int j = 0; j < 8; j++) acc[i][j] = fmaf(a[i], w[j], acc[i][j]);
        }
        __syncthreads();
    }
    // epilogue + bias
    float4 b0 = *(const float4*)&g_bcat[tc * 8];
    float4 b1 = *(const float4*)&g_bcat[tc * 8 + 4];
    #pragma unroll
    for (int i = 0; i < 4; i++) {
        int row = block_m + tr * 4 + i;
        if (row < n) {
            float4 o0 = make_float4(acc[i][0] + b0.x, acc[i][1] + b0.y,
                                    acc[i][2] + b0.z, acc[i][3] + b0.w);
            float4 o1 = make_float4(acc[i][4] + b1.x, acc[i][5] + b1.y,
                                    acc[i][6] + b1.z, acc[i][7] + b1.w);
            *(float4*)&g_xlr[row * 128 + tc * 8] = o0;
            *(float4*)&g_xlr[row * 128 + tc * 8 + 4] = o1;
        }
    }
}

// ---------------- fused GATv2 message passing (online softmax), warp/node -----
__global__ void gat_edge_kernel(const float* __restrict__ We,
                                const float* __restrict__ att,
                                const float* __restrict__ bias, int n) {
    int warp = (blockIdx.x * blockDim.x + threadIdx.x) >> 5;
    int lane = threadIdx.x & 31;
    if (warp >= n) return;
    int v = warp;

    float2 xr = *(const float2*)&g_xlr[v * 128 + 64 + 2 * lane];
    float2 we = *(const float2*)&We[2 * lane];
    float2 at = *(const float2*)&att[2 * lane];

    int beg = g_rowptr[v], end = g_rowptr[v + 1];
    float m = -INFINITY, denom = 0.0f;
    float2 acc = make_float2(0.0f, 0.0f);

    for (int j = beg; j < end; ++j) {
        int   s  = __ldg(&g_colsrc[j]);
        float ea = __ldg(&g_colea[j]);
        float2 xs = *(const float2*)&g_xlr[s * 128 + 2 * lane];
        float s0 = fmaf(ea, we.x, xs.x + xr.x);
        float s1 = fmaf(ea, we.y, xs.y + xr.y);
        s0 = (s0 > 0.0f) ? s0 : 0.2f * s0;     // leaky_relu(0.2)
        s1 = (s1 > 0.0f) ? s1 : 0.2f * s1;
        float part = fmaf(s0, at.x, s1 * at.y);
        part += __shfl_xor_sync(0xffffffffu, part, 16);
        part += __shfl_xor_sync(0xffffffffu, part, 8);
        part += __shfl_xor_sync(0xffffffffu, part, 4);
        part += __shfl_xor_sync(0xffffffffu, part, 2);
        part += __shfl_xor_sync(0xffffffffu, part, 1);
        float logit = part;
        float nm    = fmaxf(m, logit);
        float scale = __expf(m - nm);          // exp(-inf)=0 on first edge
        float p     = __expf(logit - nm);
        denom = fmaf(denom, scale, p);
        acc.x = fmaf(acc.x, scale, p * xs.x);
        acc.y = fmaf(acc.y, scale, p * xs.y);
        m = nm;
    }
    float inv = 1.0f / (denom + 1e-16f);
    float o0 = fmaf(acc.x, inv, bias[2 * lane]);
    float o1 = fmaf(acc.y, inv, bias[2 * lane + 1]);
    o0 = (o0 > 0.0f) ? o0 : (__expf(o0) - 1.0f);   // ELU
    o1 = (o1 > 0.0f) ? o1 : (__expf(o1) - 1.0f);
    ((float2*)g_h)[v * 32 + lane] = make_float2(o0, o1);
}

// ---------------- global mean pool (batch sorted -> contiguous ranges) --------
__global__ void pool_kernel(const int* __restrict__ batch, int n) {
    int g = blockIdx.x;
    int lo = 0, hi = n;
    while (lo < hi) { int mid = (lo + hi) >> 1; if (batch[mid] < g) lo = mid + 1; else hi = mid; }
    int beg = lo;
    lo = beg; hi = n;
    while (lo < hi) { int mid = (lo + hi) >> 1; if (batch[mid] < g + 1) lo = mid + 1; else hi = mid; }
    int end = lo;

    int c = threadIdx.x & 63;
    int slice = threadIdx.x >> 6;   // 0..3
    float accv = 0.0f;
    for (int i = beg + slice; i < end; i += 4) accv += g_h[i * 64 + c];
    __shared__ float sm[4][64];
    sm[slice][c] = accv;
    __syncthreads();
    if (threadIdx.x < 64) {
        float s = sm[0][c] + sm[1][c] + sm[2][c] + sm[3][c];
        int cnt = end - beg;
        g_pooled[g * 64 + c] = s / (float)max(cnt, 1);
    }
}

// ---------------- head: fc1 -> relu -> BN -> fc3 ------------------------------
__global__ void head_kernel(const float* __restrict__ W_fc1, const float* __restrict__ b_fc1,
                            const float* __restrict__ gamma, const float* __restrict__ beta,
                            const float* __restrict__ mean,  const float* __restrict__ var,
                            const float* __restrict__ W_fc3, const float* __restrict__ b_fc3,
                            float* __restrict__ out) {
    int g = blockIdx.x, lane = threadIdx.x;     // 32 threads
    float acc = b_fc1[lane];
    #pragma unroll 8
    for (int k = 0; k < 64; k++) acc = fmaf(g_pooled[g * 64 + k], W_fc1[k * 32 + lane], acc);
    float z = fmaxf(acc, 0.0f);
    z = (z - mean[lane]) * rsqrtf(var[lane] + 1e-5f) * gamma[lane] + beta[lane];
    float part = z * W_fc3[lane];
    part += __shfl_xor_sync(0xffffffffu, part, 16);
    part += __shfl_xor_sync(0xffffffffu, part, 8);
    part += __shfl_xor_sync(0xffffffffu, part, 4);
    part += __shfl_xor_sync(0xffffffffu, part, 2);
    part += __shfl_xor_sync(0xffffffffu, part, 1);
    if (lane == 0) out[g] = part + b_fc3[0];
}

// ---------------- launch ------------------------------------------------------
extern "C" void kernel_launch(void* const* d_in, const int* in_sizes, int n_in,
                              void* d_out, int out_size) {
    const float* x     = (const float*)d_in[0];
    const int*   ei    = (const int*)  d_in[1];
    const float* ea    = (const float*)d_in[2];
    const int*   batch = (const int*)  d_in[3];
    const float* Wl1 = (const float*)d_in[4],  *bl1 = (const float*)d_in[5];
    const float* Wr1 = (const float*)d_in[6],  *br1 = (const float*)d_in[7];
    const float* We1 = (const float*)d_in[8],  *att1 = (const float*)d_in[9];
    const float* bias1 = (const float*)d_in[10];
    const float* Wl2 = (const float*)d_in[11], *bl2 = (const float*)d_in[12];
    const float* Wr2 = (const float*)d_in[13], *br2 = (const float*)d_in[14];
    const float* We2 = (const float*)d_in[15], *att2 = (const float*)d_in[16];
    const float* bias2 = (const float*)d_in[17];
    const float* W_fc1 = (const float*)d_in[18], *b_fc1 = (const float*)d_in[19];
    const float* gamma = (const float*)d_in[20], *beta  = (const float*)d_in[21];
    const float* mean  = (const float*)d_in[22], *var   = (const float*)d_in[23];
    const float* W_fc3 = (const float*)d_in[24], *b_fc3 = (const float*)d_in[25];
    float* out = (float*)d_out;

    int n = in_sizes[0] / 128;     // 50000
    int E = in_sizes[1] / 2;       // 1.6M
    const int* src = ei;
    const int* dst = ei + E;

    // CSR build
    zero_kernel<<<(n + 255) / 256, 256>>>(n);
    edge_stats_kernel<<<(E + 255) / 256, 256>>>(dst, ea, E);
    scan_kernel<<<1, 1024>>>(n);
    scatter_kernel<<<(E + n + 255) / 256, 256>>>(src, dst, ea, E, n);

    int gemm_blocks = (n + 63) / 64;
    int edge_blocks = (n + 7) / 8;    // 8 warps/block, warp per node

    // Layer 1
    wprep_kernel<<<(128 * 128 + 255) / 256, 256>>>(Wl1, bl1, Wr1, br1, 128);
    sgemm_kernel<<<gemm_blocks, 256>>>(x, n, 128, 0);
    gat_edge_kernel<<<edge_blocks, 256>>>(We1, att1, bias1, n);

    // Layer 2
    wprep_kernel<<<(64 * 128 + 255) / 256, 256>>>(Wl2, bl2, Wr2, br2, 64);
    sgemm_kernel<<<gemm_blocks, 256>>>(nullptr, n, 64, 1);
    gat_edge_kernel<<<edge_blocks, 256>>>(We2, att2, bias2, n);

    // Pool + head
    pool_kernel<<<64, 256>>>(batch, n);
    head_kernel<<<64, 32>>>(W_fc1, b_fc1, gamma, beta, mean, var, W_fc3, b_fc3, out);
}